// round 1
// baseline (speedup 1.0000x reference)
#include <cuda_runtime.h>
#include <cuda_bf16.h>
#include <math.h>

// Problem constants
constexpr int Bc = 8;
constexpr int Sc = 512;
constexpr int Ec = 1024;
constexpr int Hc = 16;
constexpr int Dc = 64;
constexpr int Mrows = Bc * Sc;   // 4096

// Scratch (static device arrays: allocation-free)
__device__ float g_Q[(size_t)Bc * Hc * Sc * Dc];   // [B,H,S,D] 16MB
__device__ float g_K[(size_t)Bc * Hc * Sc * Dc];
__device__ float g_V[(size_t)Bc * Hc * Sc * Dc];
__device__ float g_ctx[(size_t)Mrows * Ec];        // [B,S,E] 16MB

// ---------------------------------------------------------------------------
// GEMM: out = A @ W^T + bias.  A:[M,K] row-major, W:[N,K] row-major.
// M=4096, N=1024, K=1024. Tile 128x128x16, 256 threads, 8x8 per thread.
// scatter==0: write to [B,H,S,D] layout (QKV).  scatter==1: plain [M,N].
// ---------------------------------------------------------------------------
__global__ __launch_bounds__(256, 2)
void gemm_kernel(const float* __restrict__ A,
                 const float* __restrict__ W,
                 const float* __restrict__ bias,
                 float* __restrict__ out, int scatter)
{
    __shared__ float As[16][128];
    __shared__ float Bs[16][128];

    const int tid = threadIdx.x;
    const int tx = tid & 15;       // 0..15 -> n micro
    const int ty = tid >> 4;       // 0..15 -> m micro
    const int m0 = blockIdx.y * 128;
    const int n0 = blockIdx.x * 128;

    float acc[8][8] = {};

    const int lr = tid >> 2;          // 0..63
    const int lc = (tid & 3) * 4;     // 0,4,8,12

    const float* Ap = A + (size_t)(m0 + lr) * Ec + lc;
    const float* Wp = W + (size_t)(n0 + lr) * Ec + lc;

    for (int k0 = 0; k0 < Ec; k0 += 16) {
        #pragma unroll
        for (int h = 0; h < 2; h++) {
            float4 av = *(const float4*)(Ap + (size_t)h * 64 * Ec + k0);
            int r = lr + h * 64;
            As[lc + 0][r] = av.x; As[lc + 1][r] = av.y;
            As[lc + 2][r] = av.z; As[lc + 3][r] = av.w;
            float4 bv = *(const float4*)(Wp + (size_t)h * 64 * Ec + k0);
            Bs[lc + 0][r] = bv.x; Bs[lc + 1][r] = bv.y;
            Bs[lc + 2][r] = bv.z; Bs[lc + 3][r] = bv.w;
        }
        __syncthreads();
        #pragma unroll
        for (int kk = 0; kk < 16; kk++) {
            float a[8], b[8];
            *(float4*)&a[0] = *(const float4*)&As[kk][ty * 8];
            *(float4*)&a[4] = *(const float4*)&As[kk][ty * 8 + 4];
            *(float4*)&b[0] = *(const float4*)&Bs[kk][tx * 8];
            *(float4*)&b[4] = *(const float4*)&Bs[kk][tx * 8 + 4];
            #pragma unroll
            for (int i = 0; i < 8; i++)
                #pragma unroll
                for (int j = 0; j < 8; j++)
                    acc[i][j] += a[i] * b[j];
        }
        __syncthreads();
    }

    #pragma unroll
    for (int i = 0; i < 8; i++) {
        const int m = m0 + ty * 8 + i;
        #pragma unroll
        for (int j = 0; j < 8; j++) {
            const int n = n0 + tx * 8 + j;
            float v = acc[i][j] + bias[n];
            if (scatter == 0) {
                const int b = m >> 9;          // m / S
                const int s = m & (Sc - 1);
                const int hh = n >> 6;         // n / D
                const int d = n & (Dc - 1);
                out[((((size_t)b * Hc + hh) * Sc + s) << 6) + d] = v;
            } else {
                out[(size_t)m * Ec + n] = v;
            }
        }
    }
}

// ---------------------------------------------------------------------------
// RoPE (interleaved pairs) + L2 norm. One warp per (b,h,s) row, D=64.
// ---------------------------------------------------------------------------
__global__ void rope_l2(float* __restrict__ T,
                        const float* __restrict__ cosT,
                        const float* __restrict__ sinT)
{
    const int row = blockIdx.x * 8 + (threadIdx.x >> 5);   // [0, B*H*S)
    const int lane = threadIdx.x & 31;
    const int s = row & (Sc - 1);

    float2* p = (float2*)(T + (size_t)row * Dc);
    float2 v = p[lane];
    const float c = cosT[s * 32 + lane];
    const float sn = sinT[s * 32 + lane];
    const float r0 = v.x * c - v.y * sn;
    const float r1 = v.x * sn + v.y * c;

    float ss = r0 * r0 + r1 * r1;
    #pragma unroll
    for (int o = 16; o; o >>= 1) ss += __shfl_xor_sync(0xffffffffu, ss, o);
    const float inv = 1.0f / fmaxf(sqrtf(ss), 1e-12f);

    p[lane] = make_float2(r0 * inv, r1 * inv);
}

// ---------------------------------------------------------------------------
// Attention: one block = (b,h) + a 64-row q tile. Full 64x512 score strip in
// smem -> exact softmax without a global scratch. 256 threads.
// smem: Qs[64][64] | Kbuf[64][68] (K as [k][d], later V^T as [d][k]) | Ss[64][512]
// ---------------------------------------------------------------------------
constexpr int KP = 68;  // pitch for K/V^T tiles (16B-aligned, conflict-free reads)
constexpr int SMEM_ATTN = (64 * 64 + 64 * KP + 64 * 512) * 4;  // 164864 B

__global__ __launch_bounds__(256, 1)
void attn_kernel(const float* __restrict__ Q,
                 const float* __restrict__ K,
                 const float* __restrict__ V,
                 float* __restrict__ ctx,
                 const float* __restrict__ tempPtr)
{
    extern __shared__ float sm[];
    float* Qs = sm;                       // 64*64
    float* Kb = sm + 64 * 64;             // 64*KP
    float* Ss = sm + 64 * 64 + 64 * KP;   // 64*512

    const int tid = threadIdx.x;
    const int tx = tid & 15;
    const int ty = tid >> 4;
    const int qt = blockIdx.x;            // 0..7
    const int bh = blockIdx.y;            // 0..127
    const int bb = bh >> 4;
    const int hh = bh & 15;

    const float temp = *tempPtr;
    const size_t head_off = (size_t)bh * Sc * Dc;

    // Load Q tile (scaled by temperature)
    {
        const float4* src = (const float4*)(Q + head_off + (size_t)qt * 64 * Dc);
        float4* dst = (float4*)Qs;
        for (int i = tid; i < 1024; i += 256) {
            float4 v = src[i];
            v.x *= temp; v.y *= temp; v.z *= temp; v.w *= temp;
            dst[i] = v;
        }
    }

    // ---- QK^T: fill Ss[64][512] ----
    for (int kt = 0; kt < 8; kt++) {
        const float4* Ksrc = (const float4*)(K + head_off + (size_t)kt * 64 * Dc);
        for (int i = tid; i < 1024; i += 256) {
            const int r = i >> 4, c4 = i & 15;
            *(float4*)&Kb[r * KP + c4 * 4] = Ksrc[i];
        }
        __syncthreads();

        float c[4][4] = {};
        #pragma unroll 4
        for (int d4 = 0; d4 < 16; d4++) {
            float4 a[4], b[4];
            #pragma unroll
            for (int i = 0; i < 4; i++)
                a[i] = *(const float4*)&Qs[(ty + i * 16) * 64 + d4 * 4];
            #pragma unroll
            for (int j = 0; j < 4; j++)
                b[j] = *(const float4*)&Kb[(tx + j * 16) * KP + d4 * 4];
            #pragma unroll
            for (int i = 0; i < 4; i++)
                #pragma unroll
                for (int j = 0; j < 4; j++)
                    c[i][j] += a[i].x * b[j].x + a[i].y * b[j].y
                             + a[i].z * b[j].z + a[i].w * b[j].w;
        }
        #pragma unroll
        for (int i = 0; i < 4; i++)
            #pragma unroll
            for (int j = 0; j < 4; j++)
                Ss[(ty + i * 16) * 512 + kt * 64 + tx + j * 16] = c[i][j];
        __syncthreads();
    }

    // ---- softmax per row ----
    {
        const int wid = tid >> 5, lane = tid & 31;
        for (int r = wid; r < 64; r += 8) {
            float* row = Ss + r * 512;
            float mx = -1e30f;
            for (int i = lane; i < 512; i += 32) mx = fmaxf(mx, row[i]);
            #pragma unroll
            for (int o = 16; o; o >>= 1)
                mx = fmaxf(mx, __shfl_xor_sync(0xffffffffu, mx, o));
            float sum = 0.f;
            for (int i = lane; i < 512; i += 32) {
                const float e = expf(row[i] - mx);
                row[i] = e;
                sum += e;
            }
            #pragma unroll
            for (int o = 16; o; o >>= 1)
                sum += __shfl_xor_sync(0xffffffffu, sum, o);
            const float inv = 1.f / sum;
            for (int i = lane; i < 512; i += 32) row[i] *= inv;
        }
    }
    __syncthreads();

    // ---- P @ V ----
    float o[4][4] = {};
    for (int kt = 0; kt < 8; kt++) {
        // load V tile transposed into Kb: Kb[d][k]
        const float4* Vsrc = (const float4*)(V + head_off + (size_t)kt * 64 * Dc);
        for (int i = tid; i < 1024; i += 256) {
            const int r = i >> 4, c = (i & 15) * 4;
            float4 v = Vsrc[i];
            Kb[(c + 0) * KP + r] = v.x;
            Kb[(c + 1) * KP + r] = v.y;
            Kb[(c + 2) * KP + r] = v.z;
            Kb[(c + 3) * KP + r] = v.w;
        }
        __syncthreads();

        #pragma unroll 4
        for (int k4 = 0; k4 < 16; k4++) {
            float4 a[4], b[4];
            #pragma unroll
            for (int i = 0; i < 4; i++)
                a[i] = *(const float4*)&Ss[(ty + i * 16) * 512 + kt * 64 + k4 * 4];
            #pragma unroll
            for (int j = 0; j < 4; j++)
                b[j] = *(const float4*)&Kb[(tx + j * 16) * KP + k4 * 4];
            #pragma unroll
            for (int i = 0; i < 4; i++)
                #pragma unroll
                for (int j = 0; j < 4; j++)
                    o[i][j] += a[i].x * b[j].x + a[i].y * b[j].y
                             + a[i].z * b[j].z + a[i].w * b[j].w;
        }
        __syncthreads();
    }

    // store ctx[b][s][h*64+d]
    #pragma unroll
    for (int i = 0; i < 4; i++) {
        const int s = qt * 64 + ty + i * 16;
        #pragma unroll
        for (int j = 0; j < 4; j++) {
            const int d = tx + j * 16;
            ctx[((size_t)bb * Sc + s) * Ec + hh * Dc + d] = o[i][j];
        }
    }
}

// ---------------------------------------------------------------------------
extern "C" void kernel_launch(void* const* d_in, const int* in_sizes, int n_in,
                              void* d_out, int out_size)
{
    const float* x_q  = (const float*)d_in[0];
    const float* x_k  = (const float*)d_in[1];
    const float* x_v  = (const float*)d_in[2];
    const float* Wq   = (const float*)d_in[3];
    const float* bq   = (const float*)d_in[4];
    const float* Wk   = (const float*)d_in[5];
    const float* bk   = (const float*)d_in[6];
    const float* Wv   = (const float*)d_in[7];
    const float* bv   = (const float*)d_in[8];
    const float* Wo   = (const float*)d_in[9];
    const float* bo   = (const float*)d_in[10];
    const float* temp = (const float*)d_in[11];
    const float* cosT = (const float*)d_in[12];
    const float* sinT = (const float*)d_in[13];
    float* out = (float*)d_out;

    float *pQ, *pK, *pV, *pC;
    cudaGetSymbolAddress((void**)&pQ, g_Q);
    cudaGetSymbolAddress((void**)&pK, g_K);
    cudaGetSymbolAddress((void**)&pV, g_V);
    cudaGetSymbolAddress((void**)&pC, g_ctx);

    const dim3 ggrid(Ec / 128, Mrows / 128);   // (8, 32)

    gemm_kernel<<<ggrid, 256>>>(x_q, Wq, bq, pQ, 0);
    gemm_kernel<<<ggrid, 256>>>(x_k, Wk, bk, pK, 0);
    gemm_kernel<<<ggrid, 256>>>(x_v, Wv, bv, pV, 0);

    rope_l2<<<(Bc * Hc * Sc) / 8, 256>>>(pQ, cosT, sinT);
    rope_l2<<<(Bc * Hc * Sc) / 8, 256>>>(pK, cosT, sinT);

    cudaFuncSetAttribute(attn_kernel,
                         cudaFuncAttributeMaxDynamicSharedMemorySize, SMEM_ATTN);
    attn_kernel<<<dim3(8, Bc * Hc), 256, SMEM_ATTN>>>(pQ, pK, pV, pC, temp);

    gemm_kernel<<<ggrid, 256>>>(pC, Wo, bo, out, 1);
}

// round 3
// speedup vs baseline: 1.9441x; 1.9441x over previous
#include <cuda_runtime.h>
#include <cuda_bf16.h>
#include <math.h>
#include <cstdint>

// Problem constants
constexpr int Bc = 8;
constexpr int Sc = 512;
constexpr int Ec = 1024;
constexpr int Hc = 16;
constexpr int Dc = 64;
constexpr int Mrows = Bc * Sc;   // 4096

// Scratch (static device arrays: allocation-free)
__device__ float g_Q[(size_t)Mrows * Ec];
__device__ float g_K[(size_t)Mrows * Ec];
__device__ float g_V[(size_t)Mrows * Ec];
__device__ float g_ctx[(size_t)Mrows * Ec];

// ---------------------------------------------------------------------------
// helpers
// ---------------------------------------------------------------------------
__device__ __forceinline__ uint32_t s2u(const void* p) {
    uint32_t a;
    asm("{ .reg .u64 t; cvta.to.shared.u64 t, %1; cvt.u32.u64 %0, t; }"
        : "=r"(a) : "l"(p));
    return a;
}

__device__ __forceinline__ void cp_async16(uint32_t saddr, const void* gaddr) {
    asm volatile("cp.async.cg.shared.global [%0], [%1], 16;" :: "r"(saddr), "l"(gaddr));
}
#define CP_COMMIT() asm volatile("cp.async.commit_group;" ::: "memory")
#define CP_WAIT(n)  asm volatile("cp.async.wait_group %0;" :: "n"(n) : "memory")

__device__ __forceinline__ uint32_t to_tf32(float f) {
    uint32_t u;
    asm("cvt.rna.tf32.f32 %0, %1;" : "=r"(u) : "f"(f));
    return u;
}

__device__ __forceinline__ void mma_tf32(float* d, const uint32_t* a, const uint32_t* b) {
    asm volatile(
        "mma.sync.aligned.m16n8k8.row.col.f32.tf32.tf32.f32 "
        "{%0,%1,%2,%3}, {%4,%5,%6,%7}, {%8,%9}, {%0,%1,%2,%3};"
        : "+f"(d[0]), "+f"(d[1]), "+f"(d[2]), "+f"(d[3])
        : "r"(a[0]), "r"(a[1]), "r"(a[2]), "r"(a[3]), "r"(b[0]), "r"(b[1]));
}

// ---------------------------------------------------------------------------
// tf32 HMMA GEMM: out = A @ W^T + bias. A:[M,1024], W:[N,1024], K-major.
// CTA tile 128x128, BK=32, 3-stage cp.async pipeline, pitch-36 smem
// (conflict-free scalar fragment LDS). 8 warps (2m x 4n), warp tile 64x32.
// scatter==0 -> [B,H,S,D] layout; scatter==1 -> plain [M,N].
// ---------------------------------------------------------------------------
constexpr int BK = 32;
constexpr int PITCH = 36;                 // 36 % 32 == 4 -> conflict-free frags
constexpr int STAGES = 3;
constexpr int TILE_F = 128 * PITCH;       // floats per A (or B) tile
constexpr int STAGE_F = 2 * TILE_F;
constexpr int NCH = Ec / BK;              // 32
constexpr int SMEM_GEMM = STAGES * STAGE_F * 4;   // 110592 B

__global__ __launch_bounds__(256, 2)
void gemm_tf32(const float* __restrict__ A, const float* __restrict__ W,
               const float* __restrict__ bias, float* __restrict__ out, int scatter)
{
    extern __shared__ float sm[];
    const int tid = threadIdx.x;
    const int lane = tid & 31;
    const int wid = tid >> 5;
    const int warp_m = wid >> 2;          // 0..1
    const int warp_n = wid & 3;           // 0..3
    const int g = lane >> 2;              // 0..7
    const int t = lane & 3;               // 0..3
    const int m0 = blockIdx.y * 128;
    const int n0 = blockIdx.x * 128;

    float d[4][4][4];
    #pragma unroll
    for (int i = 0; i < 4; i++)
        #pragma unroll
        for (int j = 0; j < 4; j++)
            #pragma unroll
            for (int k = 0; k < 4; k++) d[i][j][k] = 0.f;

    const float* gA0 = A + (size_t)m0 * Ec;
    const float* gW0 = W + (size_t)n0 * Ec;
    const int row_ld = tid >> 3;          // 0..31 (x8 per pass covers 128 rows? no:)
    // loader mapping: 1024 chunks per tile, 256 threads -> 4 chunks each
    auto load_stage = [&](int c) {
        float* As = sm + (c % STAGES) * STAGE_F;
        float* Bs = As + TILE_F;
        const float* gA = gA0 + c * BK;
        const float* gW = gW0 + c * BK;
        #pragma unroll
        for (int i = 0; i < 4; i++) {
            const int idx = tid + i * 256;       // 0..1023
            const int row = idx >> 3, seg = idx & 7;
            cp_async16(s2u(As + row * PITCH + seg * 4),
                       gA + (size_t)row * Ec + seg * 4);
            cp_async16(s2u(Bs + row * PITCH + seg * 4),
                       gW + (size_t)row * Ec + seg * 4);
        }
    };

    load_stage(0); CP_COMMIT();
    load_stage(1); CP_COMMIT();

    for (int c = 0; c < NCH; c++) {
        CP_WAIT(1);
        __syncthreads();

        if (c + 2 < NCH) load_stage(c + 2);

        const float* As = sm + (c % STAGES) * STAGE_F;
        const float* Bs = As + TILE_F;
        const float* Abase = As + (warp_m * 64 + g) * PITCH + t;
        const float* Bbase = Bs + (warp_n * 32 + g) * PITCH + t;

        #pragma unroll
        for (int ks = 0; ks < 4; ks++) {
            uint32_t a[4][4], b[4][2];
            #pragma unroll
            for (int mt = 0; mt < 4; mt++) {
                const float* p = Abase + mt * 16 * PITCH + ks * 8;
                a[mt][0] = to_tf32(p[0]);
                a[mt][1] = to_tf32(p[8 * PITCH]);
                a[mt][2] = to_tf32(p[4]);
                a[mt][3] = to_tf32(p[8 * PITCH + 4]);
            }
            #pragma unroll
            for (int nt = 0; nt < 4; nt++) {
                const float* p = Bbase + nt * 8 * PITCH + ks * 8;
                b[nt][0] = to_tf32(p[0]);
                b[nt][1] = to_tf32(p[4]);
            }
            #pragma unroll
            for (int mt = 0; mt < 4; mt++)
                #pragma unroll
                for (int nt = 0; nt < 4; nt++)
                    mma_tf32(d[mt][nt], a[mt], b[nt]);
        }

        CP_COMMIT();
        __syncthreads();
    }

    // epilogue
    #pragma unroll
    for (int mt = 0; mt < 4; mt++) {
        #pragma unroll
        for (int nt = 0; nt < 4; nt++) {
            const int n = n0 + warp_n * 32 + nt * 8 + 2 * t;
            const float b0 = bias[n], b1 = bias[n + 1];
            #pragma unroll
            for (int half = 0; half < 2; half++) {
                const int m = m0 + warp_m * 64 + mt * 16 + g + half * 8;
                float2 v;
                v.x = d[mt][nt][half * 2 + 0] + b0;
                v.y = d[mt][nt][half * 2 + 1] + b1;
                if (scatter == 0) {
                    const int bb = m >> 9, ss = m & (Sc - 1);
                    const int hh = n >> 6, dd = n & (Dc - 1);
                    *(float2*)&out[((((size_t)bb * Hc + hh) * Sc + ss) << 6) + dd] = v;
                } else {
                    *(float2*)&out[(size_t)m * Ec + n] = v;
                }
            }
        }
    }
    (void)row_ld;
}

// ---------------------------------------------------------------------------
// RoPE (interleaved pairs) + L2 norm. One warp per (b,h,s) row, D=64.
// ---------------------------------------------------------------------------
__global__ void rope_l2(float* __restrict__ T,
                        const float* __restrict__ cosT,
                        const float* __restrict__ sinT)
{
    const int row = blockIdx.x * 8 + (threadIdx.x >> 5);
    const int lane = threadIdx.x & 31;
    const int s = row & (Sc - 1);

    float2* p = (float2*)(T + (size_t)row * Dc);
    float2 v = p[lane];
    const float c = cosT[s * 32 + lane];
    const float sn = sinT[s * 32 + lane];
    const float r0 = v.x * c - v.y * sn;
    const float r1 = v.x * sn + v.y * c;

    float ss = r0 * r0 + r1 * r1;
    #pragma unroll
    for (int o = 16; o; o >>= 1) ss += __shfl_xor_sync(0xffffffffu, ss, o);
    const float inv = 1.0f / fmaxf(sqrtf(ss), 1e-12f);

    p[lane] = make_float2(r0 * inv, r1 * inv);
}

// ---------------------------------------------------------------------------
// Attention (fp32 SIMT, unchanged this round)
// ---------------------------------------------------------------------------
constexpr int KP = 68;
constexpr int SMEM_ATTN = (64 * 64 + 64 * KP + 64 * 512) * 4;

__global__ __launch_bounds__(256, 1)
void attn_kernel(const float* __restrict__ Q,
                 const float* __restrict__ K,
                 const float* __restrict__ V,
                 float* __restrict__ ctx,
                 const float* __restrict__ tempPtr)
{
    extern __shared__ float smf[];
    float* Qs = smf;
    float* Kb = smf + 64 * 64;
    float* Ss = smf + 64 * 64 + 64 * KP;

    const int tid = threadIdx.x;
    const int tx = tid & 15;
    const int ty = tid >> 4;
    const int qt = blockIdx.x;
    const int bh = blockIdx.y;
    const int bb = bh >> 4;
    const int hh = bh & 15;

    const float temp = *tempPtr;
    const size_t head_off = (size_t)bh * Sc * Dc;

    {
        const float4* src = (const float4*)(Q + head_off + (size_t)qt * 64 * Dc);
        float4* dst = (float4*)Qs;
        for (int i = tid; i < 1024; i += 256) {
            float4 v = src[i];
            v.x *= temp; v.y *= temp; v.z *= temp; v.w *= temp;
            dst[i] = v;
        }
    }

    for (int kt = 0; kt < 8; kt++) {
        const float4* Ksrc = (const float4*)(K + head_off + (size_t)kt * 64 * Dc);
        for (int i = tid; i < 1024; i += 256) {
            const int r = i >> 4, c4 = i & 15;
            *(float4*)&Kb[r * KP + c4 * 4] = Ksrc[i];
        }
        __syncthreads();

        float c[4][4] = {};
        #pragma unroll 4
        for (int d4 = 0; d4 < 16; d4++) {
            float4 a[4], b[4];
            #pragma unroll
            for (int i = 0; i < 4; i++)
                a[i] = *(const float4*)&Qs[(ty + i * 16) * 64 + d4 * 4];
            #pragma unroll
            for (int j = 0; j < 4; j++)
                b[j] = *(const float4*)&Kb[(tx + j * 16) * KP + d4 * 4];
            #pragma unroll
            for (int i = 0; i < 4; i++)
                #pragma unroll
                for (int j = 0; j < 4; j++)
                    c[i][j] += a[i].x * b[j].x + a[i].y * b[j].y
                             + a[i].z * b[j].z + a[i].w * b[j].w;
        }
        #pragma unroll
        for (int i = 0; i < 4; i++)
            #pragma unroll
            for (int j = 0; j < 4; j++)
                Ss[(ty + i * 16) * 512 + kt * 64 + tx + j * 16] = c[i][j];
        __syncthreads();
    }

    {
        const int wid = tid >> 5, lane = tid & 31;
        for (int r = wid; r < 64; r += 8) {
            float* row = Ss + r * 512;
            float mx = -1e30f;
            for (int i = lane; i < 512; i += 32) mx = fmaxf(mx, row[i]);
            #pragma unroll
            for (int o = 16; o; o >>= 1)
                mx = fmaxf(mx, __shfl_xor_sync(0xffffffffu, mx, o));
            float sum = 0.f;
            for (int i = lane; i < 512; i += 32) {
                const float e = expf(row[i] - mx);
                row[i] = e;
                sum += e;
            }
            #pragma unroll
            for (int o = 16; o; o >>= 1)
                sum += __shfl_xor_sync(0xffffffffu, sum, o);
            const float inv = 1.f / sum;
            for (int i = lane; i < 512; i += 32) row[i] *= inv;
        }
    }
    __syncthreads();

    float o[4][4] = {};
    for (int kt = 0; kt < 8; kt++) {
        const float4* Vsrc = (const float4*)(V + head_off + (size_t)kt * 64 * Dc);
        for (int i = tid; i < 1024; i += 256) {
            const int r = i >> 4, c = (i & 15) * 4;
            float4 v = Vsrc[i];
            Kb[(c + 0) * KP + r] = v.x;
            Kb[(c + 1) * KP + r] = v.y;
            Kb[(c + 2) * KP + r] = v.z;
            Kb[(c + 3) * KP + r] = v.w;
        }
        __syncthreads();

        #pragma unroll 4
        for (int k4 = 0; k4 < 16; k4++) {
            float4 a[4], b[4];
            #pragma unroll
            for (int i = 0; i < 4; i++)
                a[i] = *(const float4*)&Ss[(ty + i * 16) * 512 + kt * 64 + k4 * 4];
            #pragma unroll
            for (int j = 0; j < 4; j++)
                b[j] = *(const float4*)&Kb[(tx + j * 16) * KP + k4 * 4];
            #pragma unroll
            for (int i = 0; i < 4; i++)
                #pragma unroll
                for (int j = 0; j < 4; j++)
                    o[i][j] += a[i].x * b[j].x + a[i].y * b[j].y
                             + a[i].z * b[j].z + a[i].w * b[j].w;
        }
        __syncthreads();
    }

    #pragma unroll
    for (int i = 0; i < 4; i++) {
        const int s = qt * 64 + ty + i * 16;
        #pragma unroll
        for (int j = 0; j < 4; j++) {
            const int d = tx + j * 16;
            ctx[((size_t)bb * Sc + s) * Ec + hh * Dc + d] = o[i][j];
        }
    }
}

// ---------------------------------------------------------------------------
extern "C" void kernel_launch(void* const* d_in, const int* in_sizes, int n_in,
                              void* d_out, int out_size)
{
    const float* x_q  = (const float*)d_in[0];
    const float* x_k  = (const float*)d_in[1];
    const float* x_v  = (const float*)d_in[2];
    const float* Wq   = (const float*)d_in[3];
    const float* bq   = (const float*)d_in[4];
    const float* Wk   = (const float*)d_in[5];
    const float* bk   = (const float*)d_in[6];
    const float* Wv   = (const float*)d_in[7];
    const float* bv   = (const float*)d_in[8];
    const float* Wo   = (const float*)d_in[9];
    const float* bo   = (const float*)d_in[10];
    const float* temp = (const float*)d_in[11];
    const float* cosT = (const float*)d_in[12];
    const float* sinT = (const float*)d_in[13];
    float* out = (float*)d_out;

    float *pQ, *pK, *pV, *pC;
    cudaGetSymbolAddress((void**)&pQ, g_Q);
    cudaGetSymbolAddress((void**)&pK, g_K);
    cudaGetSymbolAddress((void**)&pV, g_V);
    cudaGetSymbolAddress((void**)&pC, g_ctx);

    cudaFuncSetAttribute(gemm_tf32,
                         cudaFuncAttributeMaxDynamicSharedMemorySize, SMEM_GEMM);
    cudaFuncSetAttribute(attn_kernel,
                         cudaFuncAttributeMaxDynamicSharedMemorySize, SMEM_ATTN);

    const dim3 ggrid(Ec / 128, Mrows / 128);   // (8, 32)
    gemm_tf32<<<ggrid, 256, SMEM_GEMM>>>(x_q, Wq, bq, pQ, 0);
    gemm_tf32<<<ggrid, 256, SMEM_GEMM>>>(x_k, Wk, bk, pK, 0);
    gemm_tf32<<<ggrid, 256, SMEM_GEMM>>>(x_v, Wv, bv, pV, 0);

    rope_l2<<<(Bc * Hc * Sc) / 8, 256>>>(pQ, cosT, sinT);
    rope_l2<<<(Bc * Hc * Sc) / 8, 256>>>(pK, cosT, sinT);

    attn_kernel<<<dim3(8, Bc * Hc), 256, SMEM_ATTN>>>(pQ, pK, pV, pC, temp);

    gemm_tf32<<<ggrid, 256, SMEM_GEMM>>>(pC, Wo, bo, out, 1);
}

// round 4
// speedup vs baseline: 2.8184x; 1.4497x over previous
#include <cuda_runtime.h>
#include <cuda_bf16.h>
#include <math.h>
#include <cstdint>

// Problem constants
constexpr int Bc = 8;
constexpr int Sc = 512;
constexpr int Ec = 1024;
constexpr int Hc = 16;
constexpr int Dc = 64;
constexpr int Mrows = Bc * Sc;   // 4096

// Scratch (static device arrays: allocation-free)
__device__ float g_Q[(size_t)Mrows * Ec];
__device__ float g_K[(size_t)Mrows * Ec];
__device__ float g_V[(size_t)Mrows * Ec];
__device__ float g_ctx[(size_t)Mrows * Ec];
__device__ float g_cxq[(size_t)Mrows * Ec];
__device__ float g_cxk[(size_t)Mrows * Ec];
__device__ float g_cxv[(size_t)Mrows * Ec];
__device__ float g_cwq[(size_t)Ec * Ec];
__device__ float g_cwk[(size_t)Ec * Ec];
__device__ float g_cwv[(size_t)Ec * Ec];
__device__ float g_cwo[(size_t)Ec * Ec];

// ---------------------------------------------------------------------------
// helpers
// ---------------------------------------------------------------------------
__device__ __forceinline__ uint32_t s2u(const void* p) {
    uint32_t a;
    asm("{ .reg .u64 t; cvta.to.shared.u64 t, %1; cvt.u32.u64 %0, t; }"
        : "=r"(a) : "l"(p));
    return a;
}

__device__ __forceinline__ void cp_async16(uint32_t saddr, const void* gaddr) {
    asm volatile("cp.async.cg.shared.global [%0], [%1], 16;" :: "r"(saddr), "l"(gaddr));
}
#define CP_COMMIT() asm volatile("cp.async.commit_group;" ::: "memory")
#define CP_WAIT(n)  asm volatile("cp.async.wait_group %0;" :: "n"(n) : "memory")

__device__ __forceinline__ float tf32r(float f) {
    uint32_t u;
    asm("cvt.rna.tf32.f32 %0, %1;" : "=r"(u) : "f"(f));
    return __uint_as_float(u);
}

__device__ __forceinline__ void mma_tf32(float* d, const uint32_t* a, const uint32_t* b) {
    asm volatile(
        "mma.sync.aligned.m16n8k8.row.col.f32.tf32.tf32.f32 "
        "{%0,%1,%2,%3}, {%4,%5,%6,%7}, {%8,%9}, {%0,%1,%2,%3};"
        : "+f"(d[0]), "+f"(d[1]), "+f"(d[2]), "+f"(d[3])
        : "r"(a[0]), "r"(a[1]), "r"(a[2]), "r"(a[3]), "r"(b[0]), "r"(b[1]));
}

// ---------------------------------------------------------------------------
// bulk fp32 -> tf32 (round-to-nearest) pre-pass
// ---------------------------------------------------------------------------
__global__ void cvt_tf32_kernel(const float* __restrict__ in,
                                float* __restrict__ out, int n4) {
    int i = blockIdx.x * blockDim.x + threadIdx.x;
    if (i >= n4) return;
    float4 v = ((const float4*)in)[i];
    v.x = tf32r(v.x); v.y = tf32r(v.y); v.z = tf32r(v.z); v.w = tf32r(v.w);
    ((float4*)out)[i] = v;
}

// ---------------------------------------------------------------------------
// tf32 HMMA GEMM: out = A @ W^T + bias. Inputs are pre-rounded tf32 values,
// so fragments feed mma.sync directly (no cvt in hot loop).
// CTA 128x128, BK=32, 3-stage cp.async, pitch-36 smem (conflict-free frags).
// scatter==0 -> [B,H,S,D] layout; scatter==1 -> plain [M,N].
// round_out!=0 -> round outputs to tf32 before store.
// ---------------------------------------------------------------------------
constexpr int BK = 32;
constexpr int PITCH = 36;
constexpr int STAGES = 3;
constexpr int TILE_F = 128 * PITCH;
constexpr int STAGE_F = 2 * TILE_F;
constexpr int NCH = Ec / BK;              // 32
constexpr int SMEM_GEMM = STAGES * STAGE_F * 4;   // 110592 B

__global__ __launch_bounds__(256, 2)
void gemm_tf32(const float* __restrict__ A, const float* __restrict__ W,
               const float* __restrict__ bias, float* __restrict__ out,
               int scatter, int round_out)
{
    extern __shared__ float sm[];
    const int tid = threadIdx.x;
    const int lane = tid & 31;
    const int wid = tid >> 5;
    const int warp_m = wid >> 2;
    const int warp_n = wid & 3;
    const int g = lane >> 2;
    const int t = lane & 3;
    const int m0 = blockIdx.y * 128;
    const int n0 = blockIdx.x * 128;

    float d[4][4][4];
    #pragma unroll
    for (int i = 0; i < 4; i++)
        #pragma unroll
        for (int j = 0; j < 4; j++)
            #pragma unroll
            for (int k = 0; k < 4; k++) d[i][j][k] = 0.f;

    const float* gA0 = A + (size_t)m0 * Ec;
    const float* gW0 = W + (size_t)n0 * Ec;

    auto load_stage = [&](int c) {
        float* As = sm + (c % STAGES) * STAGE_F;
        float* Bs = As + TILE_F;
        const float* gA = gA0 + c * BK;
        const float* gW = gW0 + c * BK;
        #pragma unroll
        for (int i = 0; i < 4; i++) {
            const int idx = tid + i * 256;
            const int row = idx >> 3, seg = idx & 7;
            cp_async16(s2u(As + row * PITCH + seg * 4),
                       gA + (size_t)row * Ec + seg * 4);
            cp_async16(s2u(Bs + row * PITCH + seg * 4),
                       gW + (size_t)row * Ec + seg * 4);
        }
    };

    load_stage(0); CP_COMMIT();
    load_stage(1); CP_COMMIT();

    for (int c = 0; c < NCH; c++) {
        CP_WAIT(1);
        __syncthreads();

        if (c + 2 < NCH) load_stage(c + 2);

        const float* As = sm + (c % STAGES) * STAGE_F;
        const float* Bs = As + TILE_F;
        const uint32_t* Abase = (const uint32_t*)(As + (warp_m * 64 + g) * PITCH + t);
        const uint32_t* Bbase = (const uint32_t*)(Bs + (warp_n * 32 + g) * PITCH + t);

        #pragma unroll
        for (int ks = 0; ks < 4; ks++) {
            uint32_t a[4][4], b[4][2];
            #pragma unroll
            for (int mt = 0; mt < 4; mt++) {
                const uint32_t* p = Abase + mt * 16 * PITCH + ks * 8;
                a[mt][0] = p[0];
                a[mt][1] = p[8 * PITCH];
                a[mt][2] = p[4];
                a[mt][3] = p[8 * PITCH + 4];
            }
            #pragma unroll
            for (int nt = 0; nt < 4; nt++) {
                const uint32_t* p = Bbase + nt * 8 * PITCH + ks * 8;
                b[nt][0] = p[0];
                b[nt][1] = p[4];
            }
            #pragma unroll
            for (int mt = 0; mt < 4; mt++)
                #pragma unroll
                for (int nt = 0; nt < 4; nt++)
                    mma_tf32(d[mt][nt], a[mt], b[nt]);
        }

        CP_COMMIT();
        __syncthreads();
    }

    #pragma unroll
    for (int mt = 0; mt < 4; mt++) {
        #pragma unroll
        for (int nt = 0; nt < 4; nt++) {
            const int n = n0 + warp_n * 32 + nt * 8 + 2 * t;
            const float b0 = bias[n], b1 = bias[n + 1];
            #pragma unroll
            for (int half = 0; half < 2; half++) {
                const int m = m0 + warp_m * 64 + mt * 16 + g + half * 8;
                float2 v;
                v.x = d[mt][nt][half * 2 + 0] + b0;
                v.y = d[mt][nt][half * 2 + 1] + b1;
                if (round_out) { v.x = tf32r(v.x); v.y = tf32r(v.y); }
                if (scatter == 0) {
                    const int bb = m >> 9, ss = m & (Sc - 1);
                    const int hh = n >> 6, dd = n & (Dc - 1);
                    *(float2*)&out[((((size_t)bb * Hc + hh) * Sc + ss) << 6) + dd] = v;
                } else {
                    *(float2*)&out[(size_t)m * Ec + n] = v;
                }
            }
        }
    }
}

// ---------------------------------------------------------------------------
// RoPE + L2 norm; writes tf32-rounded output. One warp per (b,h,s) row.
// ---------------------------------------------------------------------------
__global__ void rope_l2(float* __restrict__ T,
                        const float* __restrict__ cosT,
                        const float* __restrict__ sinT)
{
    const int row = blockIdx.x * 8 + (threadIdx.x >> 5);
    const int lane = threadIdx.x & 31;
    const int s = row & (Sc - 1);

    float2* p = (float2*)(T + (size_t)row * Dc);
    float2 v = p[lane];
    const float c = cosT[s * 32 + lane];
    const float sn = sinT[s * 32 + lane];
    const float r0 = v.x * c - v.y * sn;
    const float r1 = v.x * sn + v.y * c;

    float ss = r0 * r0 + r1 * r1;
    #pragma unroll
    for (int o = 16; o; o >>= 1) ss += __shfl_xor_sync(0xffffffffu, ss, o);
    const float inv = 1.0f / fmaxf(sqrtf(ss), 1e-12f);

    p[lane] = make_float2(tf32r(r0 * inv), tf32r(r1 * inv));
}

// ---------------------------------------------------------------------------
// Tensor-core attention. One block = (b,h) x 64-row q tile. 256 threads.
// Q/K/V already tf32-rounded. S strip 64x512 (pitch 516) in smem; exact
// softmax; probs rounded to tf32; PV accumulated in regs; ctx written rounded.
// ---------------------------------------------------------------------------
constexpr int QP = 68;     // Q smem pitch
constexpr int KCP = 68;    // K chunk pitch (128 keys x 64 d)
constexpr int VTP = 132;   // V^T pitch (64 d x 128 keys)
constexpr int SP = 516;    // S strip pitch
constexpr int QS_F = 64 * QP;                        // 4352
constexpr int KC_F = 128 * KCP;                      // 8704 (>= 64*VTP=8448)
constexpr int SS_F = 64 * SP;                        // 33024
constexpr int SMEM_ATTN = (QS_F + KC_F + SS_F) * 4;  // 184320 B

__global__ __launch_bounds__(256, 1)
void attn_kernel(const float* __restrict__ Q,
                 const float* __restrict__ K,
                 const float* __restrict__ V,
                 float* __restrict__ ctx,
                 const float* __restrict__ tempPtr)
{
    extern __shared__ float smf[];
    float* Qs = smf;
    float* Kc = smf + QS_F;      // reused as Vt in phase 3
    float* Ss = smf + QS_F + KC_F;

    const int tid = threadIdx.x;
    const int lane = tid & 31;
    const int wid = tid >> 5;
    const int g = lane >> 2;
    const int t = lane & 3;
    const int warp_m = wid >> 2;   // 0..1
    const int warp_n = wid & 3;    // 0..3
    const int qt = blockIdx.x;
    const int bh = blockIdx.y;
    const int bb = bh >> 4;
    const int hh = bh & 15;
    const float temp = *tempPtr;
    const size_t head_off = (size_t)bh * Sc * Dc;

    // ---- load Q tile into smem ----
    {
        const float4* src = (const float4*)(Q + head_off + (size_t)qt * 64 * Dc);
        for (int i = tid; i < 1024; i += 256) {
            const int r = i >> 4, c4 = i & 15;
            *(float4*)&Qs[r * QP + c4 * 4] = src[i];
        }
    }
    __syncthreads();

    // ---- preload Q fragments (rows warp_m*32 .. +31, all 8 k-steps) ----
    uint32_t qf[2][8][4];
    {
        const uint32_t* Abase = (const uint32_t*)(Qs + (warp_m * 32 + g) * QP + t);
        #pragma unroll
        for (int mt = 0; mt < 2; mt++)
            #pragma unroll
            for (int ks = 0; ks < 8; ks++) {
                const uint32_t* p = Abase + mt * 16 * QP + ks * 8;
                qf[mt][ks][0] = p[0];
                qf[mt][ks][1] = p[8 * QP];
                qf[mt][ks][2] = p[4];
                qf[mt][ks][3] = p[8 * QP + 4];
            }
    }

    // ---- phase 1: QK^T in 4 chunks of 128 keys ----
    for (int kt = 0; kt < 4; kt++) {
        // load K chunk [128 keys][64 d] via cp.async
        const float* gK = K + head_off + (size_t)kt * 128 * Dc;
        #pragma unroll
        for (int i = 0; i < 8; i++) {
            const int idx = tid + i * 256;           // 0..2047
            const int r = idx >> 4, seg = idx & 15;
            cp_async16(s2u(Kc + r * KCP + seg * 4),
                       gK + (size_t)r * Dc + seg * 4);
        }
        CP_COMMIT();
        CP_WAIT(0);
        __syncthreads();

        float sacc[2][4][4];
        #pragma unroll
        for (int i = 0; i < 2; i++)
            #pragma unroll
            for (int j = 0; j < 4; j++)
                #pragma unroll
                for (int k = 0; k < 4; k++) sacc[i][j][k] = 0.f;

        const uint32_t* Bbase = (const uint32_t*)(Kc + (warp_n * 32 + g) * KCP + t);
        #pragma unroll
        for (int ks = 0; ks < 8; ks++) {
            uint32_t b[4][2];
            #pragma unroll
            for (int nt = 0; nt < 4; nt++) {
                const uint32_t* p = Bbase + nt * 8 * KCP + ks * 8;
                b[nt][0] = p[0];
                b[nt][1] = p[4];
            }
            #pragma unroll
            for (int mt = 0; mt < 2; mt++)
                #pragma unroll
                for (int nt = 0; nt < 4; nt++)
                    mma_tf32(sacc[mt][nt], qf[mt][ks], b[nt]);
        }

        // store S (scaled by temperature)
        #pragma unroll
        for (int mt = 0; mt < 2; mt++)
            #pragma unroll
            for (int nt = 0; nt < 4; nt++)
                #pragma unroll
                for (int half = 0; half < 2; half++) {
                    const int r = warp_m * 32 + mt * 16 + g + half * 8;
                    const int col = kt * 128 + warp_n * 32 + nt * 8 + 2 * t;
                    float2 v;
                    v.x = sacc[mt][nt][half * 2 + 0] * temp;
                    v.y = sacc[mt][nt][half * 2 + 1] * temp;
                    *(float2*)&Ss[r * SP + col] = v;
                }
        __syncthreads();
    }

    // ---- phase 2: softmax per row; probs rounded to tf32 ----
    for (int r = wid; r < 64; r += 8) {
        float* row = Ss + r * SP;
        float mx = -1e30f;
        for (int i = lane; i < 512; i += 32) mx = fmaxf(mx, row[i]);
        #pragma unroll
        for (int o = 16; o; o >>= 1)
            mx = fmaxf(mx, __shfl_xor_sync(0xffffffffu, mx, o));
        float sum = 0.f;
        for (int i = lane; i < 512; i += 32) {
            const float e = __expf(row[i] - mx);
            row[i] = e;
            sum += e;
        }
        #pragma unroll
        for (int o = 16; o; o >>= 1)
            sum += __shfl_xor_sync(0xffffffffu, sum, o);
        const float inv = 1.f / sum;
        for (int i = lane; i < 512; i += 32) row[i] = tf32r(row[i] * inv);
    }
    __syncthreads();

    // ---- phase 3: O = P @ V in 4 chunks of 128 keys ----
    float oacc[2][2][4];
    #pragma unroll
    for (int i = 0; i < 2; i++)
        #pragma unroll
        for (int j = 0; j < 2; j++)
            #pragma unroll
            for (int k = 0; k < 4; k++) oacc[i][j][k] = 0.f;

    float* Vt = Kc;   // reuse buffer: [64 d][VTP]
    for (int kt = 0; kt < 4; kt++) {
        __syncthreads();   // previous chunk's reads done before overwrite
        const float4* gV = (const float4*)(V + head_off + (size_t)kt * 128 * Dc);
        for (int i = tid; i < 2048; i += 256) {
            const int r = i >> 4, d4 = i & 15;     // r = key, d4*4 = dim
            float4 v = gV[i];
            Vt[(d4 * 4 + 0) * VTP + r] = v.x;
            Vt[(d4 * 4 + 1) * VTP + r] = v.y;
            Vt[(d4 * 4 + 2) * VTP + r] = v.z;
            Vt[(d4 * 4 + 3) * VTP + r] = v.w;
        }
        __syncthreads();

        const uint32_t* Abase =
            (const uint32_t*)(Ss + (warp_m * 32 + g) * SP + kt * 128 + t);
        const uint32_t* Bbase =
            (const uint32_t*)(Vt + (warp_n * 16 + g) * VTP + t);

        #pragma unroll
        for (int ks = 0; ks < 16; ks++) {
            uint32_t a[2][4], b[2][2];
            #pragma unroll
            for (int mt = 0; mt < 2; mt++) {
                const uint32_t* p = Abase + mt * 16 * SP + ks * 8;
                a[mt][0] = p[0];
                a[mt][1] = p[8 * SP];
                a[mt][2] = p[4];
                a[mt][3] = p[8 * SP + 4];
            }
            #pragma unroll
            for (int nt = 0; nt < 2; nt++) {
                const uint32_t* p = Bbase + nt * 8 * VTP + ks * 8;
                b[nt][0] = p[0];
                b[nt][1] = p[4];
            }
            #pragma unroll
            for (int mt = 0; mt < 2; mt++)
                #pragma unroll
                for (int nt = 0; nt < 2; nt++)
                    mma_tf32(oacc[mt][nt], a[mt], b[nt]);
        }
    }

    // ---- epilogue: ctx[b][s][h*64+d], rounded to tf32 ----
    #pragma unroll
    for (int mt = 0; mt < 2; mt++)
        #pragma unroll
        for (int nt = 0; nt < 2; nt++)
            #pragma unroll
            for (int half = 0; half < 2; half++) {
                const int s = qt * 64 + warp_m * 32 + mt * 16 + g + half * 8;
                const int d = warp_n * 16 + nt * 8 + 2 * t;
                float2 v;
                v.x = tf32r(oacc[mt][nt][half * 2 + 0]);
                v.y = tf32r(oacc[mt][nt][half * 2 + 1]);
                *(float2*)&ctx[((size_t)bb * Sc + s) * Ec + hh * Dc + d] = v;
            }
}

// ---------------------------------------------------------------------------
extern "C" void kernel_launch(void* const* d_in, const int* in_sizes, int n_in,
                              void* d_out, int out_size)
{
    const float* x_q  = (const float*)d_in[0];
    const float* x_k  = (const float*)d_in[1];
    const float* x_v  = (const float*)d_in[2];
    const float* Wq   = (const float*)d_in[3];
    const float* bq   = (const float*)d_in[4];
    const float* Wk   = (const float*)d_in[5];
    const float* bk   = (const float*)d_in[6];
    const float* Wv   = (const float*)d_in[7];
    const float* bv   = (const float*)d_in[8];
    const float* Wo   = (const float*)d_in[9];
    const float* bo   = (const float*)d_in[10];
    const float* temp = (const float*)d_in[11];
    const float* cosT = (const float*)d_in[12];
    const float* sinT = (const float*)d_in[13];
    float* out = (float*)d_out;

    float *pQ, *pK, *pV, *pC, *cxq, *cxk, *cxv, *cwq, *cwk, *cwv, *cwo;
    cudaGetSymbolAddress((void**)&pQ, g_Q);
    cudaGetSymbolAddress((void**)&pK, g_K);
    cudaGetSymbolAddress((void**)&pV, g_V);
    cudaGetSymbolAddress((void**)&pC, g_ctx);
    cudaGetSymbolAddress((void**)&cxq, g_cxq);
    cudaGetSymbolAddress((void**)&cxk, g_cxk);
    cudaGetSymbolAddress((void**)&cxv, g_cxv);
    cudaGetSymbolAddress((void**)&cwq, g_cwq);
    cudaGetSymbolAddress((void**)&cwk, g_cwk);
    cudaGetSymbolAddress((void**)&cwv, g_cwv);
    cudaGetSymbolAddress((void**)&cwo, g_cwo);

    cudaFuncSetAttribute(gemm_tf32,
                         cudaFuncAttributeMaxDynamicSharedMemorySize, SMEM_GEMM);
    cudaFuncSetAttribute(attn_kernel,
                         cudaFuncAttributeMaxDynamicSharedMemorySize, SMEM_ATTN);

    const int nx4 = Mrows * Ec / 4;
    const int nw4 = Ec * Ec / 4;

    cvt_tf32_kernel<<<(nx4 + 255) / 256, 256>>>(x_q, cxq, nx4);
    cvt_tf32_kernel<<<(nx4 + 255) / 256, 256>>>(x_k, cxk, nx4);
    cvt_tf32_kernel<<<(nx4 + 255) / 256, 256>>>(x_v, cxv, nx4);
    cvt_tf32_kernel<<<(nw4 + 255) / 256, 256>>>(Wq, cwq, nw4);
    cvt_tf32_kernel<<<(nw4 + 255) / 256, 256>>>(Wk, cwk, nw4);
    cvt_tf32_kernel<<<(nw4 + 255) / 256, 256>>>(Wv, cwv, nw4);
    cvt_tf32_kernel<<<(nw4 + 255) / 256, 256>>>(Wo, cwo, nw4);

    const dim3 ggrid(Ec / 128, Mrows / 128);   // (8, 32)
    gemm_tf32<<<ggrid, 256, SMEM_GEMM>>>(cxq, cwq, bq, pQ, 0, 0);
    gemm_tf32<<<ggrid, 256, SMEM_GEMM>>>(cxk, cwk, bk, pK, 0, 0);
    gemm_tf32<<<ggrid, 256, SMEM_GEMM>>>(cxv, cwv, bv, pV, 0, 1);   // V rounded

    rope_l2<<<(Bc * Hc * Sc) / 8, 256>>>(pQ, cosT, sinT);
    rope_l2<<<(Bc * Hc * Sc) / 8, 256>>>(pK, cosT, sinT);

    attn_kernel<<<dim3(8, Bc * Hc), 256, SMEM_ATTN>>>(pQ, pK, pV, pC, temp);

    gemm_tf32<<<ggrid, 256, SMEM_GEMM>>>(pC, cwo, bo, out, 1, 0);
}

// round 5
// speedup vs baseline: 2.9776x; 1.0565x over previous
#include <cuda_runtime.h>
#include <cuda_bf16.h>
#include <math.h>
#include <cstdint>

// Problem constants
constexpr int Bc = 8;
constexpr int Sc = 512;
constexpr int Ec = 1024;
constexpr int Hc = 16;
constexpr int Dc = 64;
constexpr int Mrows = Bc * Sc;   // 4096

// Scratch (static device arrays: allocation-free)
__device__ float g_Q[(size_t)Mrows * Ec];
__device__ float g_K[(size_t)Mrows * Ec];
__device__ float g_V[(size_t)Mrows * Ec];
__device__ float g_ctx[(size_t)Mrows * Ec];
__device__ float g_cxq[(size_t)Mrows * Ec];
__device__ float g_cxk[(size_t)Mrows * Ec];
__device__ float g_cxv[(size_t)Mrows * Ec];
__device__ float g_cwq[(size_t)Ec * Ec];
__device__ float g_cwk[(size_t)Ec * Ec];
__device__ float g_cwv[(size_t)Ec * Ec];
__device__ float g_cwo[(size_t)Ec * Ec];

// ---------------------------------------------------------------------------
// helpers
// ---------------------------------------------------------------------------
__device__ __forceinline__ uint32_t s2u(const void* p) {
    uint32_t a;
    asm("{ .reg .u64 t; cvta.to.shared.u64 t, %1; cvt.u32.u64 %0, t; }"
        : "=r"(a) : "l"(p));
    return a;
}

__device__ __forceinline__ void cp_async16(uint32_t saddr, const void* gaddr) {
    asm volatile("cp.async.cg.shared.global [%0], [%1], 16;" :: "r"(saddr), "l"(gaddr));
}
#define CP_COMMIT() asm volatile("cp.async.commit_group;" ::: "memory")
#define CP_WAIT(n)  asm volatile("cp.async.wait_group %0;" :: "n"(n) : "memory")

__device__ __forceinline__ float tf32r(float f) {
    uint32_t u;
    asm("cvt.rna.tf32.f32 %0, %1;" : "=r"(u) : "f"(f));
    return __uint_as_float(u);
}

__device__ __forceinline__ void mma_tf32(float* d, const uint32_t* a, const uint32_t* b) {
    asm volatile(
        "mma.sync.aligned.m16n8k8.row.col.f32.tf32.tf32.f32 "
        "{%0,%1,%2,%3}, {%4,%5,%6,%7}, {%8,%9}, {%0,%1,%2,%3};"
        : "+f"(d[0]), "+f"(d[1]), "+f"(d[2]), "+f"(d[3])
        : "r"(a[0]), "r"(a[1]), "r"(a[2]), "r"(a[3]), "r"(b[0]), "r"(b[1]));
}

// ldmatrix x4: loads 4 8x4(b32) matrices; works for tf32 (16B rows).
__device__ __forceinline__ void ldsm4(uint32_t* r, const void* smem_ptr) {
    uint32_t a = s2u(smem_ptr);
    asm volatile("ldmatrix.sync.aligned.m8n8.x4.shared.b16 {%0,%1,%2,%3}, [%4];"
                 : "=r"(r[0]), "=r"(r[1]), "=r"(r[2]), "=r"(r[3]) : "r"(a));
}

// ---------------------------------------------------------------------------
// bulk fp32 -> tf32 pre-pass: blockIdx.y selects one of up to 4 tensors
// ---------------------------------------------------------------------------
__global__ void cvt_tf32_multi(const float* in0, const float* in1,
                               const float* in2, const float* in3,
                               float* o0, float* o1, float* o2, float* o3,
                               int n4) {
    const float* in = blockIdx.y == 0 ? in0 : blockIdx.y == 1 ? in1
                    : blockIdx.y == 2 ? in2 : in3;
    float* out = blockIdx.y == 0 ? o0 : blockIdx.y == 1 ? o1
               : blockIdx.y == 2 ? o2 : o3;
    int i = blockIdx.x * blockDim.x + threadIdx.x;
    if (i >= n4) return;
    float4 v = ((const float4*)in)[i];
    v.x = tf32r(v.x); v.y = tf32r(v.y); v.z = tf32r(v.z); v.w = tf32r(v.w);
    ((float4*)out)[i] = v;
}

// ---------------------------------------------------------------------------
// tf32 HMMA GEMM: out = A @ W^T + bias. Inputs pre-rounded tf32.
// CTA 128x128, BK=32, 3-stage cp.async, pitch-36 smem, ldmatrix frags.
// ---------------------------------------------------------------------------
constexpr int BK = 32;
constexpr int PITCH = 36;                 // 144B; 144%128==16 -> ldsm conflict-free
constexpr int STAGES = 3;
constexpr int TILE_F = 128 * PITCH;
constexpr int STAGE_F = 2 * TILE_F;
constexpr int NCH = Ec / BK;              // 32
constexpr int SMEM_GEMM = STAGES * STAGE_F * 4;   // 110592 B

__global__ __launch_bounds__(256, 2)
void gemm_tf32(const float* __restrict__ A, const float* __restrict__ W,
               const float* __restrict__ bias, float* __restrict__ out,
               int scatter, int round_out)
{
    extern __shared__ float sm[];
    const int tid = threadIdx.x;
    const int lane = tid & 31;
    const int wid = tid >> 5;
    const int warp_m = wid >> 2;
    const int warp_n = wid & 3;
    const int g = lane >> 2;
    const int t = lane & 3;
    const int m0 = blockIdx.y * 128;
    const int n0 = blockIdx.x * 128;

    // ldmatrix lane-address components
    const int aRow = warp_m * 64 + ((lane >> 3) & 1) * 8 + (lane & 7);
    const int aCol = (lane >> 4) * 4;
    const int bRow = warp_n * 32 + (lane >> 4) * 8 + (lane & 7);
    const int bCol = ((lane >> 3) & 1) * 4;

    float d[4][4][4];
    #pragma unroll
    for (int i = 0; i < 4; i++)
        #pragma unroll
        for (int j = 0; j < 4; j++)
            #pragma unroll
            for (int k = 0; k < 4; k++) d[i][j][k] = 0.f;

    const float* gA0 = A + (size_t)m0 * Ec;
    const float* gW0 = W + (size_t)n0 * Ec;

    auto load_stage = [&](int c) {
        float* As = sm + (c % STAGES) * STAGE_F;
        float* Bs = As + TILE_F;
        const float* gA = gA0 + c * BK;
        const float* gW = gW0 + c * BK;
        #pragma unroll
        for (int i = 0; i < 4; i++) {
            const int idx = tid + i * 256;
            const int row = idx >> 3, seg = idx & 7;
            cp_async16(s2u(As + row * PITCH + seg * 4),
                       gA + (size_t)row * Ec + seg * 4);
            cp_async16(s2u(Bs + row * PITCH + seg * 4),
                       gW + (size_t)row * Ec + seg * 4);
        }
    };

    load_stage(0); CP_COMMIT();
    load_stage(1); CP_COMMIT();

    for (int c = 0; c < NCH; c++) {
        CP_WAIT(1);
        __syncthreads();

        if (c + 2 < NCH) load_stage(c + 2);

        const float* As = sm + (c % STAGES) * STAGE_F;
        const float* Bs = As + TILE_F;

        #pragma unroll
        for (int ks = 0; ks < 4; ks++) {
            uint32_t a[4][4], b[4][2];
            #pragma unroll
            for (int mt = 0; mt < 4; mt++)
                ldsm4(a[mt], As + (aRow + mt * 16) * PITCH + ks * 8 + aCol);
            ldsm4(&b[0][0], Bs + bRow * PITCH + ks * 8 + bCol);          // nt 0,1
            ldsm4(&b[2][0], Bs + (bRow + 16) * PITCH + ks * 8 + bCol);   // nt 2,3
            #pragma unroll
            for (int mt = 0; mt < 4; mt++)
                #pragma unroll
                for (int nt = 0; nt < 4; nt++)
                    mma_tf32(d[mt][nt], a[mt], b[nt]);
        }

        CP_COMMIT();
        __syncthreads();
    }

    #pragma unroll
    for (int mt = 0; mt < 4; mt++) {
        #pragma unroll
        for (int nt = 0; nt < 4; nt++) {
            const int n = n0 + warp_n * 32 + nt * 8 + 2 * t;
            const float b0 = bias[n], b1 = bias[n + 1];
            #pragma unroll
            for (int half = 0; half < 2; half++) {
                const int m = m0 + warp_m * 64 + mt * 16 + g + half * 8;
                float2 v;
                v.x = d[mt][nt][half * 2 + 0] + b0;
                v.y = d[mt][nt][half * 2 + 1] + b1;
                if (round_out) { v.x = tf32r(v.x); v.y = tf32r(v.y); }
                if (scatter == 0) {
                    const int bb = m >> 9, ss = m & (Sc - 1);
                    const int hh = n >> 6, dd = n & (Dc - 1);
                    *(float2*)&out[((((size_t)bb * Hc + hh) * Sc + ss) << 6) + dd] = v;
                } else {
                    *(float2*)&out[(size_t)m * Ec + n] = v;
                }
            }
        }
    }
}

// ---------------------------------------------------------------------------
// RoPE + L2 norm (Q and K in one launch); writes tf32-rounded output.
// ---------------------------------------------------------------------------
__global__ void rope_l2(float* __restrict__ TQ, float* __restrict__ TK,
                        const float* __restrict__ cosT,
                        const float* __restrict__ sinT)
{
    float* T = blockIdx.y ? TK : TQ;
    const int row = blockIdx.x * 8 + (threadIdx.x >> 5);
    const int lane = threadIdx.x & 31;
    const int s = row & (Sc - 1);

    float2* p = (float2*)(T + (size_t)row * Dc);
    float2 v = p[lane];
    const float c = cosT[s * 32 + lane];
    const float sn = sinT[s * 32 + lane];
    const float r0 = v.x * c - v.y * sn;
    const float r1 = v.x * sn + v.y * c;

    float ss = r0 * r0 + r1 * r1;
    #pragma unroll
    for (int o = 16; o; o >>= 1) ss += __shfl_xor_sync(0xffffffffu, ss, o);
    const float inv = 1.0f / fmaxf(sqrtf(ss), 1e-12f);

    p[lane] = make_float2(tf32r(r0 * inv), tf32r(r1 * inv));
}

// ---------------------------------------------------------------------------
// Tensor-core attention with ldmatrix fragment loads.
// ---------------------------------------------------------------------------
constexpr int QP = 68;     // 272B % 128 == 16 -> ldsm conflict-free
constexpr int KCP = 68;
constexpr int VTP = 132;   // 528B % 128 == 16
constexpr int SP = 516;    // 2064B % 128 == 16
constexpr int QS_F = 64 * QP;
constexpr int KC_F = 128 * KCP;
constexpr int SS_F = 64 * SP;
constexpr int SMEM_ATTN = (QS_F + KC_F + SS_F) * 4;  // 184320 B

__global__ __launch_bounds__(256, 1)
void attn_kernel(const float* __restrict__ Q,
                 const float* __restrict__ K,
                 const float* __restrict__ V,
                 float* __restrict__ ctx,
                 const float* __restrict__ tempPtr)
{
    extern __shared__ float smf[];
    float* Qs = smf;
    float* Kc = smf + QS_F;      // reused as Vt in phase 3
    float* Ss = smf + QS_F + KC_F;

    const int tid = threadIdx.x;
    const int lane = tid & 31;
    const int wid = tid >> 5;
    const int g = lane >> 2;
    const int t = lane & 3;
    const int warp_m = wid >> 2;   // 0..1
    const int warp_n = wid & 3;    // 0..3
    const int qt = blockIdx.x;
    const int bh = blockIdx.y;
    const int bb = bh >> 4;
    const int hh = bh & 15;
    const float temp = *tempPtr;
    const size_t head_off = (size_t)bh * Sc * Dc;

    // ldmatrix lane components
    const int lr8 = ((lane >> 3) & 1) * 8 + (lane & 7);   // A-style row
    const int lc4 = (lane >> 4) * 4;                      // A-style col
    const int br16 = (lane >> 4) * 8 + (lane & 7);        // B-style row (x4 = 2 tiles)
    const int bc4 = ((lane >> 3) & 1) * 4;                // B-style col

    // ---- load Q tile into smem ----
    {
        const float4* src = (const float4*)(Q + head_off + (size_t)qt * 64 * Dc);
        for (int i = tid; i < 1024; i += 256) {
            const int r = i >> 4, c4 = i & 15;
            *(float4*)&Qs[r * QP + c4 * 4] = src[i];
        }
    }
    __syncthreads();

    // ---- preload Q fragments via ldmatrix ----
    uint32_t qf[2][8][4];
    #pragma unroll
    for (int mt = 0; mt < 2; mt++)
        #pragma unroll
        for (int ks = 0; ks < 8; ks++)
            ldsm4(qf[mt][ks],
                  Qs + (warp_m * 32 + mt * 16 + lr8) * QP + ks * 8 + lc4);

    // ---- phase 1: QK^T in 4 chunks of 128 keys ----
    for (int kt = 0; kt < 4; kt++) {
        const float* gK = K + head_off + (size_t)kt * 128 * Dc;
        #pragma unroll
        for (int i = 0; i < 8; i++) {
            const int idx = tid + i * 256;
            const int r = idx >> 4, seg = idx & 15;
            cp_async16(s2u(Kc + r * KCP + seg * 4),
                       gK + (size_t)r * Dc + seg * 4);
        }
        CP_COMMIT();
        CP_WAIT(0);
        __syncthreads();

        float sacc[2][4][4];
        #pragma unroll
        for (int i = 0; i < 2; i++)
            #pragma unroll
            for (int j = 0; j < 4; j++)
                #pragma unroll
                for (int k = 0; k < 4; k++) sacc[i][j][k] = 0.f;

        #pragma unroll
        for (int ks = 0; ks < 8; ks++) {
            uint32_t b[4][2];
            ldsm4(&b[0][0], Kc + (warp_n * 32 + br16) * KCP + ks * 8 + bc4);
            ldsm4(&b[2][0], Kc + (warp_n * 32 + 16 + br16) * KCP + ks * 8 + bc4);
            #pragma unroll
            for (int mt = 0; mt < 2; mt++)
                #pragma unroll
                for (int nt = 0; nt < 4; nt++)
                    mma_tf32(sacc[mt][nt], qf[mt][ks], b[nt]);
        }

        #pragma unroll
        for (int mt = 0; mt < 2; mt++)
            #pragma unroll
            for (int nt = 0; nt < 4; nt++)
                #pragma unroll
                for (int half = 0; half < 2; half++) {
                    const int r = warp_m * 32 + mt * 16 + g + half * 8;
                    const int col = kt * 128 + warp_n * 32 + nt * 8 + 2 * t;
                    float2 v;
                    v.x = sacc[mt][nt][half * 2 + 0] * temp;
                    v.y = sacc[mt][nt][half * 2 + 1] * temp;
                    *(float2*)&Ss[r * SP + col] = v;
                }
        __syncthreads();
    }

    // ---- phase 2: softmax per row; probs rounded to tf32 ----
    for (int r = wid; r < 64; r += 8) {
        float* row = Ss + r * SP;
        float mx = -1e30f;
        for (int i = lane; i < 512; i += 32) mx = fmaxf(mx, row[i]);
        #pragma unroll
        for (int o = 16; o; o >>= 1)
            mx = fmaxf(mx, __shfl_xor_sync(0xffffffffu, mx, o));
        float sum = 0.f;
        for (int i = lane; i < 512; i += 32) {
            const float e = __expf(row[i] - mx);
            row[i] = e;
            sum += e;
        }
        #pragma unroll
        for (int o = 16; o; o >>= 1)
            sum += __shfl_xor_sync(0xffffffffu, sum, o);
        const float inv = 1.f / sum;
        for (int i = lane; i < 512; i += 32) row[i] = tf32r(row[i] * inv);
    }
    __syncthreads();

    // ---- phase 3: O = P @ V in 4 chunks of 128 keys ----
    float oacc[2][2][4];
    #pragma unroll
    for (int i = 0; i < 2; i++)
        #pragma unroll
        for (int j = 0; j < 2; j++)
            #pragma unroll
            for (int k = 0; k < 4; k++) oacc[i][j][k] = 0.f;

    float* Vt = Kc;
    for (int kt = 0; kt < 4; kt++) {
        __syncthreads();
        const float4* gV = (const float4*)(V + head_off + (size_t)kt * 128 * Dc);
        for (int i = tid; i < 2048; i += 256) {
            const int r = i >> 4, d4 = i & 15;
            float4 v = gV[i];
            Vt[(d4 * 4 + 0) * VTP + r] = v.x;
            Vt[(d4 * 4 + 1) * VTP + r] = v.y;
            Vt[(d4 * 4 + 2) * VTP + r] = v.z;
            Vt[(d4 * 4 + 3) * VTP + r] = v.w;
        }
        __syncthreads();

        #pragma unroll
        for (int ks = 0; ks < 16; ks++) {
            uint32_t a[2][4], b[2][2];
            #pragma unroll
            for (int mt = 0; mt < 2; mt++)
                ldsm4(a[mt], Ss + (warp_m * 32 + mt * 16 + lr8) * SP
                              + kt * 128 + ks * 8 + lc4);
            ldsm4(&b[0][0], Vt + (warp_n * 16 + br16) * VTP + ks * 8 + bc4);
            #pragma unroll
            for (int mt = 0; mt < 2; mt++)
                #pragma unroll
                for (int nt = 0; nt < 2; nt++)
                    mma_tf32(oacc[mt][nt], a[mt], b[nt]);
        }
    }

    // ---- epilogue ----
    #pragma unroll
    for (int mt = 0; mt < 2; mt++)
        #pragma unroll
        for (int nt = 0; nt < 2; nt++)
            #pragma unroll
            for (int half = 0; half < 2; half++) {
                const int s = qt * 64 + warp_m * 32 + mt * 16 + g + half * 8;
                const int d = warp_n * 16 + nt * 8 + 2 * t;
                float2 v;
                v.x = tf32r(oacc[mt][nt][half * 2 + 0]);
                v.y = tf32r(oacc[mt][nt][half * 2 + 1]);
                *(float2*)&ctx[((size_t)bb * Sc + s) * Ec + hh * Dc + d] = v;
            }
}

// ---------------------------------------------------------------------------
extern "C" void kernel_launch(void* const* d_in, const int* in_sizes, int n_in,
                              void* d_out, int out_size)
{
    const float* x_q  = (const float*)d_in[0];
    const float* x_k  = (const float*)d_in[1];
    const float* x_v  = (const float*)d_in[2];
    const float* Wq   = (const float*)d_in[3];
    const float* bq   = (const float*)d_in[4];
    const float* Wk   = (const float*)d_in[5];
    const float* bk   = (const float*)d_in[6];
    const float* Wv   = (const float*)d_in[7];
    const float* bv   = (const float*)d_in[8];
    const float* Wo   = (const float*)d_in[9];
    const float* bo   = (const float*)d_in[10];
    const float* temp = (const float*)d_in[11];
    const float* cosT = (const float*)d_in[12];
    const float* sinT = (const float*)d_in[13];
    float* out = (float*)d_out;

    float *pQ, *pK, *pV, *pC, *cxq, *cxk, *cxv, *cwq, *cwk, *cwv, *cwo;
    cudaGetSymbolAddress((void**)&pQ, g_Q);
    cudaGetSymbolAddress((void**)&pK, g_K);
    cudaGetSymbolAddress((void**)&pV, g_V);
    cudaGetSymbolAddress((void**)&pC, g_ctx);
    cudaGetSymbolAddress((void**)&cxq, g_cxq);
    cudaGetSymbolAddress((void**)&cxk, g_cxk);
    cudaGetSymbolAddress((void**)&cxv, g_cxv);
    cudaGetSymbolAddress((void**)&cwq, g_cwq);
    cudaGetSymbolAddress((void**)&cwk, g_cwk);
    cudaGetSymbolAddress((void**)&cwv, g_cwv);
    cudaGetSymbolAddress((void**)&cwo, g_cwo);

    cudaFuncSetAttribute(gemm_tf32,
                         cudaFuncAttributeMaxDynamicSharedMemorySize, SMEM_GEMM);
    cudaFuncSetAttribute(attn_kernel,
                         cudaFuncAttributeMaxDynamicSharedMemorySize, SMEM_ATTN);

    const int nx4 = Mrows * Ec / 4;
    const int nw4 = Ec * Ec / 4;

    // 3 inputs in one launch; 4 weights in one launch
    cvt_tf32_multi<<<dim3((nx4 + 255) / 256, 3), 256>>>(
        x_q, x_k, x_v, x_v, cxq, cxk, cxv, cxv, nx4);
    cvt_tf32_multi<<<dim3((nw4 + 255) / 256, 4), 256>>>(
        Wq, Wk, Wv, Wo, cwq, cwk, cwv, cwo, nw4);

    const dim3 ggrid(Ec / 128, Mrows / 128);   // (8, 32)
    gemm_tf32<<<ggrid, 256, SMEM_GEMM>>>(cxq, cwq, bq, pQ, 0, 0);
    gemm_tf32<<<ggrid, 256, SMEM_GEMM>>>(cxk, cwk, bk, pK, 0, 0);
    gemm_tf32<<<ggrid, 256, SMEM_GEMM>>>(cxv, cwv, bv, pV, 0, 1);

    rope_l2<<<dim3((Bc * Hc * Sc) / 8, 2), 256>>>(pQ, pK, cosT, sinT);

    attn_kernel<<<dim3(8, Bc * Hc), 256, SMEM_ATTN>>>(pQ, pK, pV, pC, temp);

    gemm_tf32<<<ggrid, 256, SMEM_GEMM>>>(pC, cwo, bo, out, 1, 0);
}

// round 6
// speedup vs baseline: 3.5521x; 1.1929x over previous
#include <cuda_runtime.h>
#include <cuda_bf16.h>
#include <math.h>
#include <cstdint>

// Problem constants
constexpr int Bc = 8;
constexpr int Sc = 512;
constexpr int Ec = 1024;
constexpr int Hc = 16;
constexpr int Dc = 64;
constexpr int Mrows = Bc * Sc;   // 4096

// Scratch (static device arrays: allocation-free)
__device__ float g_Q[(size_t)Mrows * Ec];
__device__ float g_K[(size_t)Mrows * Ec];
__device__ float g_V[(size_t)Mrows * Ec];
__device__ float g_ctx[(size_t)Mrows * Ec];
__device__ float g_cxq[(size_t)Mrows * Ec];
__device__ float g_cxk[(size_t)Mrows * Ec];
__device__ float g_cxv[(size_t)Mrows * Ec];
__device__ float g_cwq[(size_t)Ec * Ec];
__device__ float g_cwk[(size_t)Ec * Ec];
__device__ float g_cwv[(size_t)Ec * Ec];
__device__ float g_cwo[(size_t)Ec * Ec];

// ---------------------------------------------------------------------------
// helpers
// ---------------------------------------------------------------------------
__device__ __forceinline__ uint32_t s2u(const void* p) {
    uint32_t a;
    asm("{ .reg .u64 t; cvta.to.shared.u64 t, %1; cvt.u32.u64 %0, t; }"
        : "=r"(a) : "l"(p));
    return a;
}

__device__ __forceinline__ void cp_async16(uint32_t saddr, const void* gaddr) {
    asm volatile("cp.async.cg.shared.global [%0], [%1], 16;" :: "r"(saddr), "l"(gaddr));
}
#define CP_COMMIT() asm volatile("cp.async.commit_group;" ::: "memory")
#define CP_WAIT(n)  asm volatile("cp.async.wait_group %0;" :: "n"(n) : "memory")

__device__ __forceinline__ float tf32r(float f) {
    uint32_t u;
    asm("cvt.rna.tf32.f32 %0, %1;" : "=r"(u) : "f"(f));
    return __uint_as_float(u);
}

__device__ __forceinline__ void mma_tf32(float* d, const uint32_t* a, const uint32_t* b) {
    asm volatile(
        "mma.sync.aligned.m16n8k8.row.col.f32.tf32.tf32.f32 "
        "{%0,%1,%2,%3}, {%4,%5,%6,%7}, {%8,%9}, {%0,%1,%2,%3};"
        : "+f"(d[0]), "+f"(d[1]), "+f"(d[2]), "+f"(d[3])
        : "r"(a[0]), "r"(a[1]), "r"(a[2]), "r"(a[3]), "r"(b[0]), "r"(b[1]));
}

__device__ __forceinline__ void ldsm4(uint32_t* r, const void* smem_ptr) {
    uint32_t a = s2u(smem_ptr);
    asm volatile("ldmatrix.sync.aligned.m8n8.x4.shared.b16 {%0,%1,%2,%3}, [%4];"
                 : "=r"(r[0]), "=r"(r[1]), "=r"(r[2]), "=r"(r[3]) : "r"(a));
}

// ---------------------------------------------------------------------------
// bulk fp32 -> tf32 pre-pass
// ---------------------------------------------------------------------------
__global__ void cvt_tf32_multi(const float* in0, const float* in1,
                               const float* in2, const float* in3,
                               float* o0, float* o1, float* o2, float* o3,
                               int n4) {
    const float* in = blockIdx.y == 0 ? in0 : blockIdx.y == 1 ? in1
                    : blockIdx.y == 2 ? in2 : in3;
    float* out = blockIdx.y == 0 ? o0 : blockIdx.y == 1 ? o1
               : blockIdx.y == 2 ? o2 : o3;
    int i = blockIdx.x * blockDim.x + threadIdx.x;
    if (i >= n4) return;
    float4 v = ((const float4*)in)[i];
    v.x = tf32r(v.x); v.y = tf32r(v.y); v.z = tf32r(v.z); v.w = tf32r(v.w);
    ((float4*)out)[i] = v;
}

// ---------------------------------------------------------------------------
// tf32 HMMA GEMM body (shared by fused QKV kernel and the final GEMM)
// ---------------------------------------------------------------------------
constexpr int BK = 32;
constexpr int PITCH = 36;
constexpr int STAGES = 3;
constexpr int TILE_F = 128 * PITCH;
constexpr int STAGE_F = 2 * TILE_F;
constexpr int NCH = Ec / BK;
constexpr int SMEM_GEMM = STAGES * STAGE_F * 4;   // 110592 B

__device__ __forceinline__
void gemm_body(const float* __restrict__ A, const float* __restrict__ W,
               const float* __restrict__ bias, float* __restrict__ out,
               int scatter, int round_out, float* sm)
{
    const int tid = threadIdx.x;
    const int lane = tid & 31;
    const int wid = tid >> 5;
    const int warp_m = wid >> 2;
    const int warp_n = wid & 3;
    const int g = lane >> 2;
    const int t = lane & 3;
    const int m0 = blockIdx.y * 128;
    const int n0 = blockIdx.x * 128;

    const int aRow = warp_m * 64 + ((lane >> 3) & 1) * 8 + (lane & 7);
    const int aCol = (lane >> 4) * 4;
    const int bRow = warp_n * 32 + (lane >> 4) * 8 + (lane & 7);
    const int bCol = ((lane >> 3) & 1) * 4;

    float d[4][4][4];
    #pragma unroll
    for (int i = 0; i < 4; i++)
        #pragma unroll
        for (int j = 0; j < 4; j++)
            #pragma unroll
            for (int k = 0; k < 4; k++) d[i][j][k] = 0.f;

    const float* gA0 = A + (size_t)m0 * Ec;
    const float* gW0 = W + (size_t)n0 * Ec;

    auto load_stage = [&](int c) {
        float* As = sm + (c % STAGES) * STAGE_F;
        float* Bs = As + TILE_F;
        const float* gA = gA0 + c * BK;
        const float* gW = gW0 + c * BK;
        #pragma unroll
        for (int i = 0; i < 4; i++) {
            const int idx = tid + i * 256;
            const int row = idx >> 3, seg = idx & 7;
            cp_async16(s2u(As + row * PITCH + seg * 4),
                       gA + (size_t)row * Ec + seg * 4);
            cp_async16(s2u(Bs + row * PITCH + seg * 4),
                       gW + (size_t)row * Ec + seg * 4);
        }
    };

    load_stage(0); CP_COMMIT();
    load_stage(1); CP_COMMIT();

    for (int c = 0; c < NCH; c++) {
        CP_WAIT(1);
        __syncthreads();

        if (c + 2 < NCH) load_stage(c + 2);

        const float* As = sm + (c % STAGES) * STAGE_F;
        const float* Bs = As + TILE_F;

        #pragma unroll
        for (int ks = 0; ks < 4; ks++) {
            uint32_t a[4][4], b[4][2];
            #pragma unroll
            for (int mt = 0; mt < 4; mt++)
                ldsm4(a[mt], As + (aRow + mt * 16) * PITCH + ks * 8 + aCol);
            ldsm4(&b[0][0], Bs + bRow * PITCH + ks * 8 + bCol);
            ldsm4(&b[2][0], Bs + (bRow + 16) * PITCH + ks * 8 + bCol);
            #pragma unroll
            for (int mt = 0; mt < 4; mt++)
                #pragma unroll
                for (int nt = 0; nt < 4; nt++)
                    mma_tf32(d[mt][nt], a[mt], b[nt]);
        }

        CP_COMMIT();
        __syncthreads();
    }

    #pragma unroll
    for (int mt = 0; mt < 4; mt++) {
        #pragma unroll
        for (int nt = 0; nt < 4; nt++) {
            const int n = n0 + warp_n * 32 + nt * 8 + 2 * t;
            const float b0 = bias[n], b1 = bias[n + 1];
            #pragma unroll
            for (int half = 0; half < 2; half++) {
                const int m = m0 + warp_m * 64 + mt * 16 + g + half * 8;
                float2 v;
                v.x = d[mt][nt][half * 2 + 0] + b0;
                v.y = d[mt][nt][half * 2 + 1] + b1;
                if (round_out) { v.x = tf32r(v.x); v.y = tf32r(v.y); }
                if (scatter == 0) {
                    const int bb = m >> 9, ss = m & (Sc - 1);
                    const int hh = n >> 6, dd = n & (Dc - 1);
                    *(float2*)&out[((((size_t)bb * Hc + hh) * Sc + ss) << 6) + dd] = v;
                } else {
                    *(float2*)&out[(size_t)m * Ec + n] = v;
                }
            }
        }
    }
}

// Fused Q/K/V projections: blockIdx.z selects the GEMM.
__global__ __launch_bounds__(256, 2)
void gemm_qkv(const float* A0, const float* A1, const float* A2,
              const float* W0, const float* W1, const float* W2,
              const float* b0, const float* b1, const float* b2,
              float* o0, float* o1, float* o2)
{
    extern __shared__ float sm[];
    const int z = blockIdx.z;
    const float* A = z == 0 ? A0 : z == 1 ? A1 : A2;
    const float* W = z == 0 ? W0 : z == 1 ? W1 : W2;
    const float* bi = z == 0 ? b0 : z == 1 ? b1 : b2;
    float* out = z == 0 ? o0 : z == 1 ? o1 : o2;
    gemm_body(A, W, bi, out, 0, z == 2 ? 1 : 0, sm);
}

__global__ __launch_bounds__(256, 2)
void gemm_out(const float* __restrict__ A, const float* __restrict__ W,
              const float* __restrict__ bias, float* __restrict__ out)
{
    extern __shared__ float sm[];
    gemm_body(A, W, bias, out, 1, 0, sm);
}

// ---------------------------------------------------------------------------
// RoPE + L2 norm (Q and K in one launch); writes tf32-rounded output.
// ---------------------------------------------------------------------------
__global__ void rope_l2(float* __restrict__ TQ, float* __restrict__ TK,
                        const float* __restrict__ cosT,
                        const float* __restrict__ sinT)
{
    float* T = blockIdx.y ? TK : TQ;
    const int row = blockIdx.x * 8 + (threadIdx.x >> 5);
    const int lane = threadIdx.x & 31;
    const int s = row & (Sc - 1);

    float2* p = (float2*)(T + (size_t)row * Dc);
    float2 v = p[lane];
    const float c = cosT[s * 32 + lane];
    const float sn = sinT[s * 32 + lane];
    const float r0 = v.x * c - v.y * sn;
    const float r1 = v.x * sn + v.y * c;

    float ss = r0 * r0 + r1 * r1;
    #pragma unroll
    for (int o = 16; o; o >>= 1) ss += __shfl_xor_sync(0xffffffffu, ss, o);
    const float inv = 1.0f / fmaxf(sqrtf(ss), 1e-12f);

    p[lane] = make_float2(tf32r(r0 * inv), tf32r(r1 * inv));
}

// ---------------------------------------------------------------------------
// Flash attention: 128 threads, 4 warps, warp owns 16 q-rows (64-row q tile).
// Online softmax in registers; K double-buffered (cp.async); V transposed in
// smem. No S strip -> 51KB smem.
// smem: QVt[64][68] (Q tile, then reused as V^T) | Kb[2][64][68]
// ---------------------------------------------------------------------------
constexpr int AP = 68;
constexpr int FLASH_TILE = 64 * AP;                 // 4352 floats
constexpr int SMEM_FLASH = 3 * FLASH_TILE * 4;      // 52224 B

__global__ __launch_bounds__(128, 2)
void attn_flash(const float* __restrict__ Q,
                const float* __restrict__ K,
                const float* __restrict__ V,
                float* __restrict__ ctx,
                const float* __restrict__ tempPtr)
{
    extern __shared__ float smf[];
    float* QVt = smf;                     // Q tile, later V^T [d][key]
    float* Kb0 = smf + FLASH_TILE;
    float* Kb1 = smf + 2 * FLASH_TILE;

    const int tid = threadIdx.x;
    const int lane = tid & 31;
    const int warp = tid >> 5;            // 0..3, owns rows 16*warp..+15
    const int g = lane >> 2;
    const int t = lane & 3;
    const int qt = blockIdx.x;            // 0..7
    const int bh = blockIdx.y;            // 0..127
    const int bb = bh >> 4;
    const int hh = bh & 15;
    const float temp = *tempPtr;
    const size_t head_off = (size_t)bh * Sc * Dc;

    // ldmatrix lane components
    const int lr8 = ((lane >> 3) & 1) * 8 + (lane & 7);
    const int lc4 = (lane >> 4) * 4;
    const int br16 = (lane >> 4) * 8 + (lane & 7);
    const int bc4 = ((lane >> 3) & 1) * 4;

    // V transpose mapping (2-way-max STS conflicts)
    const int vd4 = tid >> 3;             // 0..15
    const int vr0 = tid & 7;              // 0..7

    // ---- load Q tile [64][64] into smem ----
    {
        const float4* src = (const float4*)(Q + head_off + (size_t)qt * 64 * Dc);
        for (int i = tid; i < 1024; i += 128) {
            const int r = i >> 4, c4 = i & 15;
            *(float4*)&QVt[r * AP + c4 * 4] = src[i];
        }
    }
    __syncthreads();

    // ---- preload Q fragments ----
    uint32_t qf[8][4];
    #pragma unroll
    for (int ks = 0; ks < 8; ks++)
        ldsm4(qf[ks], QVt + (warp * 16 + lr8) * AP + ks * 8 + lc4);

    // online softmax state (rows g and g+8 of this warp's 16)
    float run_m0 = -1e30f, run_m1 = -1e30f;
    float run_s0 = 0.f, run_s1 = 0.f;
    float oacc[8][4];
    #pragma unroll
    for (int j = 0; j < 8; j++)
        #pragma unroll
        for (int k = 0; k < 4; k++) oacc[j][k] = 0.f;

    // prefetch K chunk 0
    {
        const float* gK = K + head_off;
        #pragma unroll
        for (int i = 0; i < 8; i++) {
            const int idx = tid + i * 128;
            const int r = idx >> 4, seg = idx & 15;
            cp_async16(s2u(Kb0 + r * AP + seg * 4), gK + (size_t)r * Dc + seg * 4);
        }
        CP_COMMIT();
    }

    const uint32_t fullm = 0xffffffffu;
    const int src0 = (lane & ~3) | (t >> 1);
    const int src1 = src0 + 2;
    const bool odd = (t & 1) != 0;

    for (int kt = 0; kt < 8; kt++) {
        float* Kc = (kt & 1) ? Kb1 : Kb0;
        float* Kn = (kt & 1) ? Kb0 : Kb1;

        // prefetch V chunk into registers (overlaps with in-flight K)
        float4 vr[8];
        {
            const float4* gV = (const float4*)(V + head_off + (size_t)kt * 64 * Dc);
            #pragma unroll
            for (int p = 0; p < 8; p++)
                vr[p] = gV[(vr0 + 8 * p) * 16 + vd4];
        }

        CP_WAIT(0);
        __syncthreads();     // K chunk ready; prev PV reads of QVt done

        // transpose-store V into QVt: QVt[d][key]
        #pragma unroll
        for (int p = 0; p < 8; p++) {
            const int key = vr0 + 8 * p;
            QVt[(vd4 * 4 + 0) * AP + key] = vr[p].x;
            QVt[(vd4 * 4 + 1) * AP + key] = vr[p].y;
            QVt[(vd4 * 4 + 2) * AP + key] = vr[p].z;
            QVt[(vd4 * 4 + 3) * AP + key] = vr[p].w;
        }

        // prefetch next K chunk
        if (kt < 7) {
            const float* gK = K + head_off + (size_t)(kt + 1) * 64 * Dc;
            #pragma unroll
            for (int i = 0; i < 8; i++) {
                const int idx = tid + i * 128;
                const int r = idx >> 4, seg = idx & 15;
                cp_async16(s2u(Kn + r * AP + seg * 4), gK + (size_t)r * Dc + seg * 4);
            }
            CP_COMMIT();
        }

        // ---- QK^T: 16 q-rows x 64 keys ----
        float s[8][4];
        #pragma unroll
        for (int j = 0; j < 8; j++)
            #pragma unroll
            for (int k = 0; k < 4; k++) s[j][k] = 0.f;

        #pragma unroll
        for (int ks = 0; ks < 8; ks++) {
            uint32_t b[4][4];   // 8 n-tiles as 4 ldsm4 pairs
            #pragma unroll
            for (int jj = 0; jj < 4; jj++)
                ldsm4(b[jj], Kc + (jj * 16 + br16) * AP + ks * 8 + bc4);
            #pragma unroll
            for (int jj = 0; jj < 4; jj++) {
                mma_tf32(s[2 * jj + 0], qf[ks], &b[jj][0]);
                mma_tf32(s[2 * jj + 1], qf[ks], &b[jj][2]);
            }
        }

        // ---- online softmax update ----
        float cm0 = -1e30f, cm1 = -1e30f;
        #pragma unroll
        for (int j = 0; j < 8; j++) {
            s[j][0] *= temp; s[j][1] *= temp; s[j][2] *= temp; s[j][3] *= temp;
            cm0 = fmaxf(cm0, fmaxf(s[j][0], s[j][1]));
            cm1 = fmaxf(cm1, fmaxf(s[j][2], s[j][3]));
        }
        cm0 = fmaxf(cm0, __shfl_xor_sync(fullm, cm0, 1));
        cm0 = fmaxf(cm0, __shfl_xor_sync(fullm, cm0, 2));
        cm1 = fmaxf(cm1, __shfl_xor_sync(fullm, cm1, 1));
        cm1 = fmaxf(cm1, __shfl_xor_sync(fullm, cm1, 2));

        const float nm0 = fmaxf(run_m0, cm0);
        const float nm1 = fmaxf(run_m1, cm1);
        const float sc0 = __expf(run_m0 - nm0);
        const float sc1 = __expf(run_m1 - nm1);
        run_m0 = nm0; run_m1 = nm1;

        float ps0 = 0.f, ps1 = 0.f;
        #pragma unroll
        for (int j = 0; j < 8; j++) {
            float p0 = __expf(s[j][0] - nm0);
            float p1 = __expf(s[j][1] - nm0);
            float p2 = __expf(s[j][2] - nm1);
            float p3 = __expf(s[j][3] - nm1);
            ps0 += p0 + p1; ps1 += p2 + p3;
            s[j][0] = tf32r(p0); s[j][1] = tf32r(p1);
            s[j][2] = tf32r(p2); s[j][3] = tf32r(p3);
        }
        ps0 += __shfl_xor_sync(fullm, ps0, 1);
        ps0 += __shfl_xor_sync(fullm, ps0, 2);
        ps1 += __shfl_xor_sync(fullm, ps1, 1);
        ps1 += __shfl_xor_sync(fullm, ps1, 2);
        run_s0 = run_s0 * sc0 + ps0;
        run_s1 = run_s1 * sc1 + ps1;

        #pragma unroll
        for (int j = 0; j < 8; j++) {
            oacc[j][0] *= sc0; oacc[j][1] *= sc0;
            oacc[j][2] *= sc1; oacc[j][3] *= sc1;
        }

        __syncthreads();     // V^T stores visible to all warps

        // ---- PV: P(16x64) @ V(64x64) ----
        #pragma unroll
        for (int k8 = 0; k8 < 8; k8++) {
            // permute prob C-frags into A-frags via quad shuffles
            float v00 = __shfl_sync(fullm, s[k8][0], src0);
            float v01 = __shfl_sync(fullm, s[k8][1], src0);
            float v02 = __shfl_sync(fullm, s[k8][2], src0);
            float v03 = __shfl_sync(fullm, s[k8][3], src0);
            float v10 = __shfl_sync(fullm, s[k8][0], src1);
            float v11 = __shfl_sync(fullm, s[k8][1], src1);
            float v12 = __shfl_sync(fullm, s[k8][2], src1);
            float v13 = __shfl_sync(fullm, s[k8][3], src1);
            uint32_t a[4];
            a[0] = __float_as_uint(odd ? v01 : v00);
            a[1] = __float_as_uint(odd ? v03 : v02);
            a[2] = __float_as_uint(odd ? v11 : v10);
            a[3] = __float_as_uint(odd ? v13 : v12);

            #pragma unroll
            for (int dj = 0; dj < 4; dj++) {
                uint32_t b[4];
                ldsm4(b, QVt + (dj * 16 + br16) * AP + k8 * 8 + bc4);
                mma_tf32(oacc[2 * dj + 0], a, &b[0]);
                mma_tf32(oacc[2 * dj + 1], a, &b[2]);
            }
        }
    }

    // ---- epilogue: normalize, round, store ctx[b][s][h*64+d] ----
    const float inv0 = 1.f / run_s0;
    const float inv1 = 1.f / run_s1;
    #pragma unroll
    for (int d8 = 0; d8 < 8; d8++) {
        const int dcol = d8 * 8 + 2 * t;
        {
            const int srow = qt * 64 + warp * 16 + g;
            float2 v;
            v.x = tf32r(oacc[d8][0] * inv0);
            v.y = tf32r(oacc[d8][1] * inv0);
            *(float2*)&ctx[((size_t)bb * Sc + srow) * Ec + hh * Dc + dcol] = v;
        }
        {
            const int srow = qt * 64 + warp * 16 + g + 8;
            float2 v;
            v.x = tf32r(oacc[d8][2] * inv1);
            v.y = tf32r(oacc[d8][3] * inv1);
            *(float2*)&ctx[((size_t)bb * Sc + srow) * Ec + hh * Dc + dcol] = v;
        }
    }
}

// ---------------------------------------------------------------------------
extern "C" void kernel_launch(void* const* d_in, const int* in_sizes, int n_in,
                              void* d_out, int out_size)
{
    const float* x_q  = (const float*)d_in[0];
    const float* x_k  = (const float*)d_in[1];
    const float* x_v  = (const float*)d_in[2];
    const float* Wq   = (const float*)d_in[3];
    const float* bq   = (const float*)d_in[4];
    const float* Wk   = (const float*)d_in[5];
    const float* bk   = (const float*)d_in[6];
    const float* Wv   = (const float*)d_in[7];
    const float* bv   = (const float*)d_in[8];
    const float* Wo   = (const float*)d_in[9];
    const float* bo   = (const float*)d_in[10];
    const float* temp = (const float*)d_in[11];
    const float* cosT = (const float*)d_in[12];
    const float* sinT = (const float*)d_in[13];
    float* out = (float*)d_out;

    float *pQ, *pK, *pV, *pC, *cxq, *cxk, *cxv, *cwq, *cwk, *cwv, *cwo;
    cudaGetSymbolAddress((void**)&pQ, g_Q);
    cudaGetSymbolAddress((void**)&pK, g_K);
    cudaGetSymbolAddress((void**)&pV, g_V);
    cudaGetSymbolAddress((void**)&pC, g_ctx);
    cudaGetSymbolAddress((void**)&cxq, g_cxq);
    cudaGetSymbolAddress((void**)&cxk, g_cxk);
    cudaGetSymbolAddress((void**)&cxv, g_cxv);
    cudaGetSymbolAddress((void**)&cwq, g_cwq);
    cudaGetSymbolAddress((void**)&cwk, g_cwk);
    cudaGetSymbolAddress((void**)&cwv, g_cwv);
    cudaGetSymbolAddress((void**)&cwo, g_cwo);

    cudaFuncSetAttribute(gemm_qkv,
                         cudaFuncAttributeMaxDynamicSharedMemorySize, SMEM_GEMM);
    cudaFuncSetAttribute(gemm_out,
                         cudaFuncAttributeMaxDynamicSharedMemorySize, SMEM_GEMM);
    cudaFuncSetAttribute(attn_flash,
                         cudaFuncAttributeMaxDynamicSharedMemorySize, SMEM_FLASH);

    const int nx4 = Mrows * Ec / 4;
    const int nw4 = Ec * Ec / 4;

    cvt_tf32_multi<<<dim3((nx4 + 255) / 256, 3), 256>>>(
        x_q, x_k, x_v, x_v, cxq, cxk, cxv, cxv, nx4);
    cvt_tf32_multi<<<dim3((nw4 + 255) / 256, 4), 256>>>(
        Wq, Wk, Wv, Wo, cwq, cwk, cwv, cwo, nw4);

    // fused Q/K/V projections (z selects)
    gemm_qkv<<<dim3(Ec / 128, Mrows / 128, 3), 256, SMEM_GEMM>>>(
        cxq, cxk, cxv, cwq, cwk, cwv, bq, bk, bv, pQ, pK, pV);

    rope_l2<<<dim3((Bc * Hc * Sc) / 8, 2), 256>>>(pQ, pK, cosT, sinT);

    attn_flash<<<dim3(8, Bc * Hc), 128, SMEM_FLASH>>>(pQ, pK, pV, pC, temp);

    gemm_out<<<dim3(Ec / 128, Mrows / 128), 256, SMEM_GEMM>>>(pC, cwo, bo, out);
}